// round 15
// baseline (speedup 1.0000x reference)
#include <cuda_runtime.h>
#include <cuda_bf16.h>
#include <cstdint>

// Problem constants
#define SEQ    1024
#define DMODEL 1024
#define BATCH  4
#define HEADS  16
#define HD     64
#define MTOT   (BATCH * SEQ)   // 4096

// ---------------------------------------------------------------------------
// Scratch (device globals — no allocation allowed)
// ---------------------------------------------------------------------------
__device__ float g_V[MTOT * DMODEL];
__device__ float g_biasK[DMODEL];

__device__ __nv_bfloat16 g_xhi[MTOT * DMODEL];
__device__ __nv_bfloat16 g_xlo[MTOT * DMODEL];
__device__ __nv_bfloat16 g_barhi[MTOT * DMODEL];
__device__ __nv_bfloat16 g_barlo[MTOT * DMODEL];
__device__ __nv_bfloat16 g_beathi[MTOT * DMODEL];
__device__ __nv_bfloat16 g_beatlo[MTOT * DMODEL];
__device__ __nv_bfloat16 g_aohi[MTOT * DMODEL];
__device__ __nv_bfloat16 g_aolo[MTOT * DMODEL];

__device__ __nv_bfloat16 g_Wqhi[DMODEL * DMODEL];
__device__ __nv_bfloat16 g_Wqlo[DMODEL * DMODEL];
__device__ __nv_bfloat16 g_Wkhi[DMODEL * DMODEL];
__device__ __nv_bfloat16 g_Wklo[DMODEL * DMODEL];
__device__ __nv_bfloat16 g_Wvhi[DMODEL * DMODEL];
__device__ __nv_bfloat16 g_Wvlo[DMODEL * DMODEL];
__device__ __nv_bfloat16 g_Wbarhi[DMODEL * DMODEL];
__device__ __nv_bfloat16 g_Wbarlo[DMODEL * DMODEL];
__device__ __nv_bfloat16 g_Wbeathi[DMODEL * DMODEL];
__device__ __nv_bfloat16 g_Wbeatlo[DMODEL * DMODEL];
__device__ __nv_bfloat16 g_Wohi[DMODEL * DMODEL];
__device__ __nv_bfloat16 g_Wolo[DMODEL * DMODEL];

// Attention operands (bf16 splits; VT is per-(b,h) transposed V)
__device__ __nv_bfloat16 g_Qshi[MTOT * DMODEL];
__device__ __nv_bfloat16 g_Qslo[MTOT * DMODEL];
__device__ __nv_bfloat16 g_Kshi[MTOT * DMODEL];
__device__ __nv_bfloat16 g_Kslo[MTOT * DMODEL];
__device__ __nv_bfloat16 g_VThi[BATCH * HEADS * HD * SEQ];
__device__ __nv_bfloat16 g_VTlo[BATCH * HEADS * HD * SEQ];

// ---------------------------------------------------------------------------
// Helpers (base-PTX only: cp.async / ldmatrix / mma.sync — NO tcgen05)
// ---------------------------------------------------------------------------
__device__ __forceinline__ uint32_t smem_to_u32(const void* smem_ptr) {
    uint32_t addr;
    asm("{ .reg .u64 tmp; cvta.to.shared.u64 tmp, %1; cvt.u32.u64 %0, tmp; }"
        : "=r"(addr) : "l"(smem_ptr));
    return addr;
}

__device__ __forceinline__ void ldsm_x4(uint32_t& r0, uint32_t& r1,
                                        uint32_t& r2, uint32_t& r3, uint32_t addr) {
    asm volatile("ldmatrix.sync.aligned.m8n8.x4.shared.b16 {%0,%1,%2,%3}, [%4];"
                 : "=r"(r0), "=r"(r1), "=r"(r2), "=r"(r3) : "r"(addr));
}

__device__ __forceinline__ void mma16816(float* d,
                                         uint32_t a0, uint32_t a1, uint32_t a2, uint32_t a3,
                                         uint32_t b0, uint32_t b1) {
    asm volatile("mma.sync.aligned.m16n8k16.row.col.f32.bf16.bf16.f32 "
                 "{%0,%1,%2,%3}, {%4,%5,%6,%7}, {%8,%9}, {%0,%1,%2,%3};"
                 : "+f"(d[0]), "+f"(d[1]), "+f"(d[2]), "+f"(d[3])
                 : "r"(a0), "r"(a1), "r"(a2), "r"(a3), "r"(b0), "r"(b1));
}

__device__ __forceinline__ uint32_t pack_bf2(float x, float y) {
    __nv_bfloat162 t = __halves2bfloat162(__float2bfloat16(x), __float2bfloat16(y));
    return *reinterpret_cast<uint32_t*>(&t);
}

// Split one fp32 value into bf16 hi + lo residual
__device__ __forceinline__ void split1(float v, __nv_bfloat16& h, __nv_bfloat16& l) {
    h = __float2bfloat16(v);
    l = __float2bfloat16(v - __bfloat162float(h));
}

// Swizzled byte offset inside a 128x32 bf16 tile (64B logical rows, two per
// 128B physical row). g = 16B group index 0..3 within the row.
// Used identically by cp.async stores and ldmatrix reads.
__device__ __forceinline__ uint32_t sw32(int row, int g) {
    int j = row >> 1;
    int slot = ((row & 1) * 4 + g) ^ (j & 7);
    return (uint32_t)(j * 128 + slot * 16);
}

// ---------------------------------------------------------------------------
// fp32 -> bf16 hi/lo split (scale folded in)
// ---------------------------------------------------------------------------
__global__ void split_f32_kernel(const float* __restrict__ src,
                                 __nv_bfloat16* __restrict__ hi,
                                 __nv_bfloat16* __restrict__ lo,
                                 float scale, int n4) {
    int i = blockIdx.x * blockDim.x + threadIdx.x;
    if (i >= n4) return;
    float4 v = ((const float4*)src)[i];
    v.x *= scale; v.y *= scale; v.z *= scale; v.w *= scale;
    __nv_bfloat16 h0, h1, h2, h3, l0, l1, l2, l3;
    split1(v.x, h0, l0); split1(v.y, h1, l1);
    split1(v.z, h2, l2); split1(v.w, h3, l3);
    __nv_bfloat162* H = (__nv_bfloat162*)hi;
    __nv_bfloat162* L = (__nv_bfloat162*)lo;
    H[2*i]   = __halves2bfloat162(h0, h1);
    H[2*i+1] = __halves2bfloat162(h2, h3);
    L[2*i]   = __halves2bfloat162(l0, l1);
    L[2*i+1] = __halves2bfloat162(l2, l3);
}

// Batched weight splits: blockIdx.y selects the job
struct SplitJobs {
    const float* src[6];
    __nv_bfloat16* hi[6];
    __nv_bfloat16* lo[6];
    float scale[6];
};
__global__ void batch_split_kernel(SplitJobs J, int n4) {
    int i = blockIdx.x * blockDim.x + threadIdx.x;
    if (i >= n4) return;
    int j = blockIdx.y;
    float sc = J.scale[j];
    float4 v = ((const float4*)J.src[j])[i];
    v.x *= sc; v.y *= sc; v.z *= sc; v.w *= sc;
    __nv_bfloat16 h0, h1, h2, h3, l0, l1, l2, l3;
    split1(v.x, h0, l0); split1(v.y, h1, l1);
    split1(v.z, h2, l2); split1(v.w, h3, l3);
    __nv_bfloat162* H = (__nv_bfloat162*)J.hi[j];
    __nv_bfloat162* L = (__nv_bfloat162*)J.lo[j];
    H[2*i]   = __halves2bfloat162(h0, h1);
    H[2*i+1] = __halves2bfloat162(h2, h3);
    L[2*i]   = __halves2bfloat162(l0, l1);
    L[2*i+1] = __halves2bfloat162(l2, l3);
}

// Gather rows of x and split to bf16 hi/lo directly
__global__ void gather_split_kernel(const float* __restrict__ x,
                                    const int* __restrict__ idx,
                                    __nv_bfloat16* __restrict__ hi,
                                    __nv_bfloat16* __restrict__ lo) {
    int s = blockIdx.x;
    int b = blockIdx.y;
    int j = idx[s] & (SEQ - 1);
    const float4* src = (const float4*)&x[((size_t)b * SEQ + j) * DMODEL];
    size_t dbase = ((size_t)b * SEQ + s) * DMODEL;
    int t = threadIdx.x;   // 256 threads, 1 float4 each
    float4 v = src[t];
    __nv_bfloat16 h0, h1, h2, h3, l0, l1, l2, l3;
    split1(v.x, h0, l0); split1(v.y, h1, l1);
    split1(v.z, h2, l2); split1(v.w, h3, l3);
    __nv_bfloat162* H = (__nv_bfloat162*)&hi[dbase + t * 4];
    __nv_bfloat162* L = (__nv_bfloat162*)&lo[dbase + t * 4];
    H[0] = __halves2bfloat162(h0, h1);
    H[1] = __halves2bfloat162(h2, h3);
    L[0] = __halves2bfloat162(l0, l1);
    L[1] = __halves2bfloat162(l2, l3);
}

__global__ void combine_bias_kernel(const float* __restrict__ bk,
                                    const float* __restrict__ bbar,
                                    const float* __restrict__ bbeat,
                                    float* __restrict__ out) {
    int i = blockIdx.x * blockDim.x + threadIdx.x;
    if (i < DMODEL) out[i] = bk[i] + 0.2f * bbar[i] + 0.1f * bbeat[i];
}

// Transpose V per (b,h): VT[b][h][d][s] = V[b*SEQ+s][h*64+d], split to bf16 hi/lo
__global__ void transpose_split_v(const float* __restrict__ V,
                                  __nv_bfloat16* __restrict__ VThi,
                                  __nv_bfloat16* __restrict__ VTlo) {
    __shared__ float tile[64][65];
    int st = blockIdx.x, h = blockIdx.y, b = blockIdx.z;
    int t = threadIdx.x;            // 256
    int r = t >> 2;                 // 0..63
    int c0 = (t & 3) * 16;
    const float4* src = (const float4*)&V[((size_t)(b * SEQ + st * 64 + r)) * DMODEL + h * HD + c0];
    #pragma unroll
    for (int i = 0; i < 4; i++) {
        float4 v = src[i];
        tile[r][c0 + i*4 + 0] = v.x;
        tile[r][c0 + i*4 + 1] = v.y;
        tile[r][c0 + i*4 + 2] = v.z;
        tile[r][c0 + i*4 + 3] = v.w;
    }
    __syncthreads();
    size_t obase = ((size_t)((b * HEADS + h) * HD + r)) * SEQ + st * 64 + c0;
    #pragma unroll
    for (int i = 0; i < 16; i++) {
        float x = tile[c0 + i][r];
        __nv_bfloat16 hi, lo;
        split1(x, hi, lo);
        VThi[obase + i] = hi;
        VTlo[obase + i] = lo;
    }
}

// ---------------------------------------------------------------------------
// HMMA split-bf16 GEMM: C = sum_t A_t @ B_t^T + bias
// CTA tile 128x128, K-chunk 32, 3-stage cp.async pipeline, 8 warps (2x4).
// Stage = 4 tiles (Ahi|Alo|Bhi|Blo) x 8KB = 32KB -> 96KB total -> 2 CTAs/SM.
// ---------------------------------------------------------------------------
struct GemmParams {
    const __nv_bfloat16* Ahi[3];
    const __nv_bfloat16* Alo[3];
    const __nv_bfloat16* Bhi[3];
    const __nv_bfloat16* Blo[3];
    const float* bias;
    float* Cf;                 // optional fp32 output (may be null)
    __nv_bfloat16* Chi;        // optional split output (may be null)
    __nv_bfloat16* Clo;
    float cscale;              // scale folded into split output
    int nterms;
};
struct GemmTriple { GemmParams p[3]; };

#define GTILE_BYTES  8192             // 128 rows x 32 cols bf16
#define GSTAGE_BYTES 32768            // 4 tiles x 8KB
#define GSMEM_TOTAL  (3 * GSTAGE_BYTES)

__device__ __forceinline__ void g_load_chunk(
    const GemmParams& P, int c, int s, uint32_t smem_u32,
    int bm, int bn, int lr, int lg)
{
    int term = c >> 5;                 // 32 chunks per term
    int kc = c & 31;
    const __nv_bfloat16* M0 = P.Ahi[term];
    const __nv_bfloat16* M1 = P.Alo[term];
    const __nv_bfloat16* M2 = P.Bhi[term];
    const __nv_bfloat16* M3 = P.Blo[term];
    uint32_t sb = smem_u32 + s * GSTAGE_BYTES;
    int colel = kc * 32 + lg * 8;
    #pragma unroll
    for (int i = 0; i < 8; i++) {
        const int mat = i >> 1;                    // compile-time per i
        const int row = (i & 1) * 64 + lr;         // lr 0..63
        const uint32_t soff = (uint32_t)mat * GTILE_BYTES + sw32(row, lg);
        const __nv_bfloat16* base = (mat == 0) ? M0 : (mat == 1) ? M1
                                   : (mat == 2) ? M2 : M3;
        const int grow = ((mat < 2) ? bm : bn) + row;
        const __nv_bfloat16* g = base + (size_t)grow * 1024 + colel;
        asm volatile("cp.async.cg.shared.global [%0], [%1], 16;"
                     :: "r"(sb + soff), "l"(g));
    }
    asm volatile("cp.async.commit_group;" ::: "memory");
}

__global__ __launch_bounds__(256, 2) void gemm_tc(GemmTriple T)
{
    extern __shared__ __align__(1024) char smem[];
    const uint32_t smem_u32 = smem_to_u32(smem);
    const GemmParams P = T.p[blockIdx.z];
    const int tid  = threadIdx.x;
    const int wid  = tid >> 5;
    const int lane = tid & 31;
    const int bm = blockIdx.y * 128;
    const int bn = blockIdx.x * 128;
    const int NC = P.nterms * 32;
    const int lr = tid >> 2;          // load row 0..63
    const int lg = tid & 3;           // load 16B group 0..3
    const int wm = wid >> 2;
    const int wn = wid & 3;

    float acc[4][4][4];
    #pragma unroll
    for (int i = 0; i < 4; i++)
        #pragma unroll
        for (int j = 0; j < 4; j++)
            #pragma unroll
            for (int r = 0; r < 4; r++) acc[i][j][r] = 0.0f;

    const int arow = wm * 64 + (lane & 15);
    const int akc  = lane >> 4;                                  // 0..1
    const int brow = wn * 32 + ((lane >> 4) << 3) + (lane & 7);
    const int bkc  = (lane >> 3) & 1;                            // 0..1

    g_load_chunk(P, 0, 0, smem_u32, bm, bn, lr, lg);
    g_load_chunk(P, 1, 1, smem_u32, bm, bn, lr, lg);
    g_load_chunk(P, 2, 2, smem_u32, bm, bn, lr, lg);

    for (int c = 0; c < NC; c++) {
        int s = c - (c / 3) * 3;
        if (c + 1 >= NC)      asm volatile("cp.async.wait_group 0;" ::: "memory");
        else if (c + 2 >= NC) asm volatile("cp.async.wait_group 1;" ::: "memory");
        else                  asm volatile("cp.async.wait_group 2;" ::: "memory");
        __syncthreads();

        const uint32_t sb  = smem_u32 + s * GSTAGE_BYTES;
        const uint32_t sAh = sb;
        const uint32_t sAl = sb + GTILE_BYTES;
        const uint32_t sBh = sb + 2 * GTILE_BYTES;
        const uint32_t sBl = sb + 3 * GTILE_BYTES;

        #pragma unroll
        for (int ks = 0; ks < 2; ks++) {           // 2 x k16 per 32-chunk
            uint32_t ah[4][4], al[4][4];
            #pragma unroll
            for (int mf = 0; mf < 4; mf++) {
                int row = arow + mf * 16;
                uint32_t off = sw32(row, ks * 2 + akc);
                ldsm_x4(ah[mf][0], ah[mf][1], ah[mf][2], ah[mf][3], sAh + off);
                ldsm_x4(al[mf][0], al[mf][1], al[mf][2], al[mf][3], sAl + off);
            }
            uint32_t bh[4][2], bl[4][2];
            #pragma unroll
            for (int pr = 0; pr < 2; pr++) {
                int row = pr * 16 + brow;
                uint32_t off = sw32(row, ks * 2 + bkc);
                ldsm_x4(bh[2*pr][0], bh[2*pr][1], bh[2*pr+1][0], bh[2*pr+1][1], sBh + off);
                ldsm_x4(bl[2*pr][0], bl[2*pr][1], bl[2*pr+1][0], bl[2*pr+1][1], sBl + off);
            }
            #pragma unroll
            for (int mf = 0; mf < 4; mf++)
                #pragma unroll
                for (int nf = 0; nf < 4; nf++) {
                    mma16816(acc[mf][nf], ah[mf][0], ah[mf][1], ah[mf][2], ah[mf][3],
                             bh[nf][0], bh[nf][1]);
                    mma16816(acc[mf][nf], ah[mf][0], ah[mf][1], ah[mf][2], ah[mf][3],
                             bl[nf][0], bl[nf][1]);
                    mma16816(acc[mf][nf], al[mf][0], al[mf][1], al[mf][2], al[mf][3],
                             bh[nf][0], bh[nf][1]);
                }
        }
        __syncthreads();
        if (c + 3 < NC)
            g_load_chunk(P, c + 3, s, smem_u32, bm, bn, lr, lg);
    }

    // Epilogue: v = acc + bias; optional fp32 store; optional bf16 hi/lo store
    const int r_in = lane >> 2;
    const int c_in = (lane & 3) * 2;
    #pragma unroll
    for (int mf = 0; mf < 4; mf++) {
        #pragma unroll
        for (int nf = 0; nf < 4; nf++) {
            int col = bn + wn * 32 + nf * 8 + c_in;
            float2 b2 = *(const float2*)&P.bias[col];
            int r1 = bm + wm * 64 + mf * 16 + r_in;
            float v00 = acc[mf][nf][0] + b2.x, v01 = acc[mf][nf][1] + b2.y;
            float v10 = acc[mf][nf][2] + b2.x, v11 = acc[mf][nf][3] + b2.y;
            size_t i0 = (size_t)r1 * 1024 + col;
            size_t i1 = (size_t)(r1 + 8) * 1024 + col;
            if (P.Cf) {
                *(float2*)&P.Cf[i0] = make_float2(v00, v01);
                *(float2*)&P.Cf[i1] = make_float2(v10, v11);
            }
            if (P.Chi) {
                float s00 = v00 * P.cscale, s01 = v01 * P.cscale;
                float s10 = v10 * P.cscale, s11 = v11 * P.cscale;
                __nv_bfloat16 h00, h01, h10, h11, l00, l01, l10, l11;
                split1(s00, h00, l00); split1(s01, h01, l01);
                split1(s10, h10, l10); split1(s11, h11, l11);
                *(__nv_bfloat162*)&P.Chi[i0] = __halves2bfloat162(h00, h01);
                *(__nv_bfloat162*)&P.Chi[i1] = __halves2bfloat162(h10, h11);
                *(__nv_bfloat162*)&P.Clo[i0] = __halves2bfloat162(l00, l01);
                *(__nv_bfloat162*)&P.Clo[i1] = __halves2bfloat162(l10, l11);
            }
        }
    }
}

// ---------------------------------------------------------------------------
// HMMA causal flash attention (unchanged from R14 — validated).
// Block = (64 q-rows, head, batch); 4 warps, each owns 16 q-rows.
// smem: Qhi|Qlo (16KB) + 2 stages x (Khi|Klo|VThi|VTlo) (32KB each) = 80KB.
// ---------------------------------------------------------------------------
#define ATTN_SMEM (16384 + 2 * 32768)

__device__ __forceinline__ void attn_load_stage(
    uint32_t sbase,
    const __nv_bfloat16* __restrict__ Khi, const __nv_bfloat16* __restrict__ Klo,
    const __nv_bfloat16* __restrict__ VThi, const __nv_bfloat16* __restrict__ VTlo,
    int b, int h, int kt, int tr, int sg)
{
    const size_t kbase = ((size_t)(b * SEQ + kt * 64)) * DMODEL + h * HD + sg * 8;
    const size_t vbase = ((size_t)((b * HEADS + h) * HD)) * SEQ + kt * 64 + sg * 8;
    #pragma unroll
    for (int rr = 0; rr < 4; rr++) {
        int row = rr * 16 + tr;
        uint32_t soff = (uint32_t)row * 128u + (uint32_t)((sg ^ (row & 7)) * 16);
        asm volatile("cp.async.cg.shared.global [%0], [%1], 16;"
                     :: "r"(sbase + soff),         "l"(Khi + kbase + (size_t)row * DMODEL));
        asm volatile("cp.async.cg.shared.global [%0], [%1], 16;"
                     :: "r"(sbase + 8192 + soff),  "l"(Klo + kbase + (size_t)row * DMODEL));
        asm volatile("cp.async.cg.shared.global [%0], [%1], 16;"
                     :: "r"(sbase + 16384 + soff), "l"(VThi + vbase + (size_t)row * SEQ));
        asm volatile("cp.async.cg.shared.global [%0], [%1], 16;"
                     :: "r"(sbase + 24576 + soff), "l"(VTlo + vbase + (size_t)row * SEQ));
    }
    asm volatile("cp.async.commit_group;" ::: "memory");
}

__global__ __launch_bounds__(128, 1) void attn_mma(
    const __nv_bfloat16* __restrict__ Qhi, const __nv_bfloat16* __restrict__ Qlo,
    const __nv_bfloat16* __restrict__ Khi, const __nv_bfloat16* __restrict__ Klo,
    const __nv_bfloat16* __restrict__ VThi, const __nv_bfloat16* __restrict__ VTlo,
    __nv_bfloat16* __restrict__ Ohi, __nv_bfloat16* __restrict__ Olo)
{
    extern __shared__ __align__(1024) char smem[];
    const uint32_t smem_u32 = smem_to_u32(smem);
    const int qb = blockIdx.x, h = blockIdx.y, b = blockIdx.z;
    const int tid = threadIdx.x, w = tid >> 5, lane = tid & 31;
    const int q0 = qb * 64;
    const int sg = tid & 7, tr = tid >> 3;

    {
        const size_t qbase = ((size_t)(b * SEQ + q0)) * DMODEL + h * HD + sg * 8;
        #pragma unroll
        for (int rr = 0; rr < 4; rr++) {
            int row = rr * 16 + tr;
            uint32_t soff = (uint32_t)row * 128u + (uint32_t)((sg ^ (row & 7)) * 16);
            asm volatile("cp.async.cg.shared.global [%0], [%1], 16;"
                         :: "r"(smem_u32 + soff),        "l"(Qhi + qbase + (size_t)row * DMODEL));
            asm volatile("cp.async.cg.shared.global [%0], [%1], 16;"
                         :: "r"(smem_u32 + 8192 + soff), "l"(Qlo + qbase + (size_t)row * DMODEL));
        }
        asm volatile("cp.async.commit_group;" ::: "memory");
    }
    attn_load_stage(smem_u32 + 16384, Khi, Klo, VThi, VTlo, b, h, 0, tr, sg);

    uint32_t qh[4][4], ql[4][4];
    float o[8][4];
    #pragma unroll
    for (int nf = 0; nf < 8; nf++)
        #pragma unroll
        for (int e = 0; e < 4; e++) o[nf][e] = 0.0f;
    float m0 = -1e30f, m1 = -1e30f, l0 = 0.0f, l1 = 0.0f;

    const int rA   = (lane & 15);
    const int kcA  = lane >> 4;
    const int rB   = ((lane >> 4) << 3) + (lane & 7);
    const int kcB  = (lane >> 3) & 1;

    for (int kt = 0; kt <= qb; kt++) {
        if (kt + 1 <= qb)
            attn_load_stage(smem_u32 + 16384 + ((kt + 1) & 1) * 32768,
                            Khi, Klo, VThi, VTlo, b, h, kt + 1, tr, sg);
        if (kt + 1 <= qb) asm volatile("cp.async.wait_group 1;" ::: "memory");
        else              asm volatile("cp.async.wait_group 0;" ::: "memory");
        __syncthreads();

        if (kt == 0) {
            #pragma unroll
            for (int ks = 0; ks < 4; ks++) {
                int row = w * 16 + rA;
                int k8 = ks * 2 + kcA;
                uint32_t off = (uint32_t)row * 128u + (uint32_t)((k8 ^ (row & 7)) << 4);
                ldsm_x4(qh[ks][0], qh[ks][1], qh[ks][2], qh[ks][3], smem_u32 + off);
                ldsm_x4(ql[ks][0], ql[ks][1], ql[ks][2], ql[ks][3], smem_u32 + 8192 + off);
            }
        }

        const uint32_t sbase = smem_u32 + 16384 + (kt & 1) * 32768;
        const uint32_t sKh = sbase, sKl = sbase + 8192;
        const uint32_t sVh = sbase + 16384, sVl = sbase + 24576;

        float s[8][4];
        #pragma unroll
        for (int nf = 0; nf < 8; nf++)
            #pragma unroll
            for (int e = 0; e < 4; e++) s[nf][e] = 0.0f;

        #pragma unroll
        for (int ks = 0; ks < 4; ks++) {
            const int k8 = ks * 2;
            uint32_t bh[8][2], bl[8][2];
            #pragma unroll
            for (int pr = 0; pr < 4; pr++) {
                int row = pr * 16 + rB;
                uint32_t off = (uint32_t)row * 128u
                             + (uint32_t)(((k8 + kcB) ^ (row & 7)) << 4);
                ldsm_x4(bh[2*pr][0], bh[2*pr][1], bh[2*pr+1][0], bh[2*pr+1][1], sKh + off);
                ldsm_x4(bl[2*pr][0], bl[2*pr][1], bl[2*pr+1][0], bl[2*pr+1][1], sKl + off);
            }
            #pragma unroll
            for (int nf = 0; nf < 8; nf++) {
                mma16816(s[nf], qh[ks][0], qh[ks][1], qh[ks][2], qh[ks][3], bh[nf][0], bh[nf][1]);
                mma16816(s[nf], qh[ks][0], qh[ks][1], qh[ks][2], qh[ks][3], bl[nf][0], bl[nf][1]);
                mma16816(s[nf], ql[ks][0], ql[ks][1], ql[ks][2], ql[ks][3], bh[nf][0], bh[nf][1]);
            }
        }

        if (kt == qb) {
            const int col0 = kt * 64 + 2 * (lane & 3);
            const int row0 = q0 + w * 16 + (lane >> 2);
            #pragma unroll
            for (int nf = 0; nf < 8; nf++) {
                int key = col0 + nf * 8;
                if (key     > row0)     s[nf][0] = -1e30f;
                if (key + 1 > row0)     s[nf][1] = -1e30f;
                if (key     > row0 + 8) s[nf][2] = -1e30f;
                if (key + 1 > row0 + 8) s[nf][3] = -1e30f;
            }
        }

        float mx0 = -1e30f, mx1 = -1e30f;
        #pragma unroll
        for (int nf = 0; nf < 8; nf++) {
            mx0 = fmaxf(mx0, fmaxf(s[nf][0], s[nf][1]));
            mx1 = fmaxf(mx1, fmaxf(s[nf][2], s[nf][3]));
        }
        mx0 = fmaxf(mx0, __shfl_xor_sync(0xFFFFFFFFu, mx0, 1));
        mx0 = fmaxf(mx0, __shfl_xor_sync(0xFFFFFFFFu, mx0, 2));
        mx1 = fmaxf(mx1, __shfl_xor_sync(0xFFFFFFFFu, mx1, 1));
        mx1 = fmaxf(mx1, __shfl_xor_sync(0xFFFFFFFFu, mx1, 2));
        float mn0 = fmaxf(m0, mx0);
        float mn1 = fmaxf(m1, mx1);
        float corr0 = __expf(m0 - mn0);
        float corr1 = __expf(m1 - mn1);
        m0 = mn0; m1 = mn1;

        float sum0 = 0.0f, sum1 = 0.0f;
        uint32_t pr_hi[8], pr8_hi[8], pr_lo[8], pr8_lo[8];
        #pragma unroll
        for (int nf = 0; nf < 8; nf++) {
            float p0 = __expf(s[nf][0] - mn0);
            float p1 = __expf(s[nf][1] - mn0);
            float p2 = __expf(s[nf][2] - mn1);
            float p3 = __expf(s[nf][3] - mn1);
            sum0 += p0 + p1;
            sum1 += p2 + p3;
            __nv_bfloat16 h0 = __float2bfloat16(p0);
            __nv_bfloat16 h1 = __float2bfloat16(p1);
            __nv_bfloat16 h2 = __float2bfloat16(p2);
            __nv_bfloat16 h3 = __float2bfloat16(p3);
            __nv_bfloat162 t0 = __halves2bfloat162(h0, h1);
            __nv_bfloat162 t1 = __halves2bfloat162(h2, h3);
            pr_hi[nf]  = *reinterpret_cast<uint32_t*>(&t0);
            pr8_hi[nf] = *reinterpret_cast<uint32_t*>(&t1);
            pr_lo[nf]  = pack_bf2(p0 - __bfloat162float(h0), p1 - __bfloat162float(h1));
            pr8_lo[nf] = pack_bf2(p2 - __bfloat162float(h2), p3 - __bfloat162float(h3));
        }
        sum0 += __shfl_xor_sync(0xFFFFFFFFu, sum0, 1);
        sum0 += __shfl_xor_sync(0xFFFFFFFFu, sum0, 2);
        sum1 += __shfl_xor_sync(0xFFFFFFFFu, sum1, 1);
        sum1 += __shfl_xor_sync(0xFFFFFFFFu, sum1, 2);
        l0 = l0 * corr0 + sum0;
        l1 = l1 * corr1 + sum1;
        #pragma unroll
        for (int nf = 0; nf < 8; nf++) {
            o[nf][0] *= corr0; o[nf][1] *= corr0;
            o[nf][2] *= corr1; o[nf][3] *= corr1;
        }

        #pragma unroll
        for (int ks = 0; ks < 4; ks++) {
            const int k8 = ks * 2;
            uint32_t vh[8][2], vl[8][2];
            #pragma unroll
            for (int pr = 0; pr < 4; pr++) {
                int row = pr * 16 + rB;
                uint32_t off = (uint32_t)row * 128u
                             + (uint32_t)(((k8 + kcB) ^ (row & 7)) << 4);
                ldsm_x4(vh[2*pr][0], vh[2*pr][1], vh[2*pr+1][0], vh[2*pr+1][1], sVh + off);
                ldsm_x4(vl[2*pr][0], vl[2*pr][1], vl[2*pr+1][0], vl[2*pr+1][1], sVl + off);
            }
            uint32_t a0h = pr_hi[2*ks],  a1h = pr8_hi[2*ks];
            uint32_t a2h = pr_hi[2*ks+1], a3h = pr8_hi[2*ks+1];
            uint32_t a0l = pr_lo[2*ks],  a1l = pr8_lo[2*ks];
            uint32_t a2l = pr_lo[2*ks+1], a3l = pr8_lo[2*ks+1];
            #pragma unroll
            for (int nf = 0; nf < 8; nf++) {
                mma16816(o[nf], a0h, a1h, a2h, a3h, vh[nf][0], vh[nf][1]);
                mma16816(o[nf], a0h, a1h, a2h, a3h, vl[nf][0], vl[nf][1]);
                mma16816(o[nf], a0l, a1l, a2l, a3l, vh[nf][0], vh[nf][1]);
            }
        }
        __syncthreads();
    }

    // Epilogue: normalize and write bf16 hi/lo split directly
    float inv0 = 1.0f / l0;
    float inv1 = 1.0f / l1;
    int row = q0 + w * 16 + (lane >> 2);
    size_t base0 = ((size_t)(b * SEQ + row)) * DMODEL + h * HD;
    #pragma unroll
    for (int nf = 0; nf < 8; nf++) {
        int col = nf * 8 + 2 * (lane & 3);
        float v00 = o[nf][0] * inv0, v01 = o[nf][1] * inv0;
        float v10 = o[nf][2] * inv1, v11 = o[nf][3] * inv1;
        __nv_bfloat16 h00, h01, h10, h11, l00, l01, l10, l11;
        split1(v00, h00, l00); split1(v01, h01, l01);
        split1(v10, h10, l10); split1(v11, h11, l11);
        size_t i0 = base0 + col;
        size_t i1 = base0 + (size_t)8 * DMODEL + col;
        *(__nv_bfloat162*)&Ohi[i0] = __halves2bfloat162(h00, h01);
        *(__nv_bfloat162*)&Ohi[i1] = __halves2bfloat162(h10, h11);
        *(__nv_bfloat162*)&Olo[i0] = __halves2bfloat162(l00, l01);
        *(__nv_bfloat162*)&Olo[i1] = __halves2bfloat162(l10, l11);
    }
}

// ---------------------------------------------------------------------------
// Launch
// ---------------------------------------------------------------------------
static float* sym_f(const void* symbol) {
    void* p = nullptr;
    cudaGetSymbolAddress(&p, (const void*)symbol);
    return (float*)p;
}

extern "C" void kernel_launch(void* const* d_in, const int* in_sizes, int n_in,
                              void* d_out, int out_size) {
    const float* x      = (const float*)d_in[0];
    const int* bar      = (const int*)d_in[2];
    const int* beat     = (const int*)d_in[3];
    const float* Wq = (const float*)d_in[4];
    const float* bq = (const float*)d_in[5];
    const float* Wk = (const float*)d_in[6];
    const float* bk = (const float*)d_in[7];
    const float* Wv = (const float*)d_in[8];
    const float* bv = (const float*)d_in[9];
    const float* Wbar  = (const float*)d_in[10];
    const float* bbar  = (const float*)d_in[11];
    const float* Wbeat = (const float*)d_in[12];
    const float* bbeat = (const float*)d_in[13];
    const float* Wo = (const float*)d_in[14];
    const float* bo = (const float*)d_in[15];
    float* out = (float*)d_out;

    float* Vp     = sym_f(g_V);
    float* biasKp = sym_f(g_biasK);

    __nv_bfloat16 *xhi, *xlo, *barhi, *barlo, *beathi, *beatlo, *aohi, *aolo;
    __nv_bfloat16 *wqhi, *wqlo, *wkhi, *wklo, *wvhi, *wvlo;
    __nv_bfloat16 *wbarhi, *wbarlo, *wbeathi, *wbeatlo, *wohi, *wolo;
    __nv_bfloat16 *qshi, *qslo, *kshi, *kslo, *vthi, *vtlo;
    cudaGetSymbolAddress((void**)&xhi, g_xhi);     cudaGetSymbolAddress((void**)&xlo, g_xlo);
    cudaGetSymbolAddress((void**)&barhi, g_barhi); cudaGetSymbolAddress((void**)&barlo, g_barlo);
    cudaGetSymbolAddress((void**)&beathi, g_beathi); cudaGetSymbolAddress((void**)&beatlo, g_beatlo);
    cudaGetSymbolAddress((void**)&aohi, g_aohi);   cudaGetSymbolAddress((void**)&aolo, g_aolo);
    cudaGetSymbolAddress((void**)&wqhi, g_Wqhi);   cudaGetSymbolAddress((void**)&wqlo, g_Wqlo);
    cudaGetSymbolAddress((void**)&wkhi, g_Wkhi);   cudaGetSymbolAddress((void**)&wklo, g_Wklo);
    cudaGetSymbolAddress((void**)&wvhi, g_Wvhi);   cudaGetSymbolAddress((void**)&wvlo, g_Wvlo);
    cudaGetSymbolAddress((void**)&wbarhi, g_Wbarhi); cudaGetSymbolAddress((void**)&wbarlo, g_Wbarlo);
    cudaGetSymbolAddress((void**)&wbeathi, g_Wbeathi); cudaGetSymbolAddress((void**)&wbeatlo, g_Wbeatlo);
    cudaGetSymbolAddress((void**)&wohi, g_Wohi);   cudaGetSymbolAddress((void**)&wolo, g_Wolo);
    cudaGetSymbolAddress((void**)&qshi, g_Qshi);   cudaGetSymbolAddress((void**)&qslo, g_Qslo);
    cudaGetSymbolAddress((void**)&kshi, g_Kshi);   cudaGetSymbolAddress((void**)&kslo, g_Kslo);
    cudaGetSymbolAddress((void**)&vthi, g_VThi);   cudaGetSymbolAddress((void**)&vtlo, g_VTlo);

    cudaFuncSetAttribute(gemm_tc, cudaFuncAttributeMaxDynamicSharedMemorySize, GSMEM_TOTAL);
    cudaFuncSetAttribute(attn_mma, cudaFuncAttributeMaxDynamicSharedMemorySize, ATTN_SMEM);

    const int NACT = MTOT * DMODEL / 4;
    const int NW   = DMODEL * DMODEL / 4;

    // Conversions: x split, gathers, 6 weight splits (one batched launch), bias combine
    split_f32_kernel<<<(NACT + 255) / 256, 256>>>(x, xhi, xlo, 1.0f, NACT);
    gather_split_kernel<<<dim3(SEQ, BATCH), 256>>>(x, bar,  barhi,  barlo);
    gather_split_kernel<<<dim3(SEQ, BATCH), 256>>>(x, beat, beathi, beatlo);
    {
        SplitJobs J;
        J.src[0] = Wq;    J.hi[0] = wqhi;    J.lo[0] = wqlo;    J.scale[0] = 1.0f;
        J.src[1] = Wk;    J.hi[1] = wkhi;    J.lo[1] = wklo;    J.scale[1] = 1.0f;
        J.src[2] = Wv;    J.hi[2] = wvhi;    J.lo[2] = wvlo;    J.scale[2] = 1.0f;
        J.src[3] = Wbar;  J.hi[3] = wbarhi;  J.lo[3] = wbarlo;  J.scale[3] = 0.2f;
        J.src[4] = Wbeat; J.hi[4] = wbeathi; J.lo[4] = wbeatlo; J.scale[4] = 0.1f;
        J.src[5] = Wo;    J.hi[5] = wohi;    J.lo[5] = wolo;    J.scale[5] = 1.0f;
        batch_split_kernel<<<dim3((NW + 255) / 256, 6), 256>>>(J, NW);
    }
    combine_bias_kernel<<<4, 256>>>(bk, bbar, bbeat, biasKp);

    // Fused Q/V/K_eff projections (grid.z selects), split outputs written directly
    {
        GemmTriple T = {};
        // z=0: Q -> split only (scale 1/8 folded)
        T.p[0].Ahi[0] = xhi; T.p[0].Alo[0] = xlo;
        T.p[0].Bhi[0] = wqhi; T.p[0].Blo[0] = wqlo;
        T.p[0].bias = bq; T.p[0].Cf = nullptr;
        T.p[0].Chi = qshi; T.p[0].Clo = qslo; T.p[0].cscale = 0.125f;
        T.p[0].nterms = 1;
        // z=1: V -> fp32 only (transpose consumes it)
        T.p[1].Ahi[0] = xhi; T.p[1].Alo[0] = xlo;
        T.p[1].Bhi[0] = wvhi; T.p[1].Blo[0] = wvlo;
        T.p[1].bias = bv; T.p[1].Cf = Vp;
        T.p[1].Chi = nullptr; T.p[1].Clo = nullptr; T.p[1].cscale = 1.0f;
        T.p[1].nterms = 1;
        // z=2: K_eff (3 terms) -> split only
        T.p[2].Ahi[0] = xhi;    T.p[2].Alo[0] = xlo;
        T.p[2].Bhi[0] = wkhi;   T.p[2].Blo[0] = wklo;
        T.p[2].Ahi[1] = barhi;  T.p[2].Alo[1] = barlo;
        T.p[2].Bhi[1] = wbarhi; T.p[2].Blo[1] = wbarlo;
        T.p[2].Ahi[2] = beathi; T.p[2].Alo[2] = beatlo;
        T.p[2].Bhi[2] = wbeathi; T.p[2].Blo[2] = wbeatlo;
        T.p[2].bias = biasKp; T.p[2].Cf = nullptr;
        T.p[2].Chi = kshi; T.p[2].Clo = kslo; T.p[2].cscale = 1.0f;
        T.p[2].nterms = 3;
        gemm_tc<<<dim3(8, 32, 3), 256, GSMEM_TOTAL>>>(T);
    }

    // V transpose + split
    transpose_split_v<<<dim3(SEQ / 64, HEADS, BATCH), 256>>>(Vp, vthi, vtlo);

    // HMMA causal attention -> writes ao hi/lo splits directly
    attn_mma<<<dim3(SEQ / 64, HEADS, BATCH), 128, ATTN_SMEM>>>(
        qshi, qslo, kshi, kslo, vthi, vtlo, aohi, aolo);

    // Output projection: out = AO @ Wo^T + bo (fp32 to d_out)
    {
        GemmTriple T = {};
        T.p[0].Ahi[0] = aohi; T.p[0].Alo[0] = aolo;
        T.p[0].Bhi[0] = wohi; T.p[0].Blo[0] = wolo;
        T.p[0].bias = bo; T.p[0].Cf = out;
        T.p[0].Chi = nullptr; T.p[0].Clo = nullptr; T.p[0].cscale = 1.0f;
        T.p[0].nterms = 1;
        gemm_tc<<<dim3(8, 32, 1), 256, GSMEM_TOTAL>>>(T);
    }
}

// round 16
// speedup vs baseline: 1.1038x; 1.1038x over previous
#include <cuda_runtime.h>
#include <cuda_bf16.h>
#include <cstdint>

// Problem constants
#define SEQ    1024
#define DMODEL 1024
#define BATCH  4
#define HEADS  16
#define HD     64
#define MTOT   (BATCH * SEQ)   // 4096

// ---------------------------------------------------------------------------
// Scratch (device globals — no allocation allowed)
// ---------------------------------------------------------------------------
__device__ float g_biasK[DMODEL];

__device__ __nv_bfloat16 g_xhi[MTOT * DMODEL];
__device__ __nv_bfloat16 g_xlo[MTOT * DMODEL];
__device__ __nv_bfloat16 g_barhi[MTOT * DMODEL];
__device__ __nv_bfloat16 g_barlo[MTOT * DMODEL];
__device__ __nv_bfloat16 g_beathi[MTOT * DMODEL];
__device__ __nv_bfloat16 g_beatlo[MTOT * DMODEL];
__device__ __nv_bfloat16 g_aohi[MTOT * DMODEL];
__device__ __nv_bfloat16 g_aolo[MTOT * DMODEL];

__device__ __nv_bfloat16 g_Wqhi[DMODEL * DMODEL];
__device__ __nv_bfloat16 g_Wqlo[DMODEL * DMODEL];
__device__ __nv_bfloat16 g_Wkhi[DMODEL * DMODEL];
__device__ __nv_bfloat16 g_Wklo[DMODEL * DMODEL];
__device__ __nv_bfloat16 g_Wvhi[DMODEL * DMODEL];
__device__ __nv_bfloat16 g_Wvlo[DMODEL * DMODEL];
__device__ __nv_bfloat16 g_Wbarhi[DMODEL * DMODEL];
__device__ __nv_bfloat16 g_Wbarlo[DMODEL * DMODEL];
__device__ __nv_bfloat16 g_Wbeathi[DMODEL * DMODEL];
__device__ __nv_bfloat16 g_Wbeatlo[DMODEL * DMODEL];
__device__ __nv_bfloat16 g_Wohi[DMODEL * DMODEL];
__device__ __nv_bfloat16 g_Wolo[DMODEL * DMODEL];

// Attention operands (bf16 splits; V now kept in row layout like K)
__device__ __nv_bfloat16 g_Qshi[MTOT * DMODEL];
__device__ __nv_bfloat16 g_Qslo[MTOT * DMODEL];
__device__ __nv_bfloat16 g_Kshi[MTOT * DMODEL];
__device__ __nv_bfloat16 g_Kslo[MTOT * DMODEL];
__device__ __nv_bfloat16 g_Vshi[MTOT * DMODEL];
__device__ __nv_bfloat16 g_Vslo[MTOT * DMODEL];

// ---------------------------------------------------------------------------
// Helpers (base-PTX only: cp.async / ldmatrix / mma.sync — NO tcgen05)
// ---------------------------------------------------------------------------
__device__ __forceinline__ uint32_t smem_to_u32(const void* smem_ptr) {
    uint32_t addr;
    asm("{ .reg .u64 tmp; cvta.to.shared.u64 tmp, %1; cvt.u32.u64 %0, tmp; }"
        : "=r"(addr) : "l"(smem_ptr));
    return addr;
}

__device__ __forceinline__ void ldsm_x4(uint32_t& r0, uint32_t& r1,
                                        uint32_t& r2, uint32_t& r3, uint32_t addr) {
    asm volatile("ldmatrix.sync.aligned.m8n8.x4.shared.b16 {%0,%1,%2,%3}, [%4];"
                 : "=r"(r0), "=r"(r1), "=r"(r2), "=r"(r3) : "r"(addr));
}

// Transposing variant: loads 4 8x8 b16 tiles and transposes each.
__device__ __forceinline__ void ldsm_x4_t(uint32_t& r0, uint32_t& r1,
                                          uint32_t& r2, uint32_t& r3, uint32_t addr) {
    asm volatile("ldmatrix.sync.aligned.m8n8.x4.trans.shared.b16 {%0,%1,%2,%3}, [%4];"
                 : "=r"(r0), "=r"(r1), "=r"(r2), "=r"(r3) : "r"(addr));
}

__device__ __forceinline__ void mma16816(float* d,
                                         uint32_t a0, uint32_t a1, uint32_t a2, uint32_t a3,
                                         uint32_t b0, uint32_t b1) {
    asm volatile("mma.sync.aligned.m16n8k16.row.col.f32.bf16.bf16.f32 "
                 "{%0,%1,%2,%3}, {%4,%5,%6,%7}, {%8,%9}, {%0,%1,%2,%3};"
                 : "+f"(d[0]), "+f"(d[1]), "+f"(d[2]), "+f"(d[3])
                 : "r"(a0), "r"(a1), "r"(a2), "r"(a3), "r"(b0), "r"(b1));
}

__device__ __forceinline__ uint32_t pack_bf2(float x, float y) {
    __nv_bfloat162 t = __halves2bfloat162(__float2bfloat16(x), __float2bfloat16(y));
    return *reinterpret_cast<uint32_t*>(&t);
}

// Split one fp32 value into bf16 hi + lo residual
__device__ __forceinline__ void split1(float v, __nv_bfloat16& h, __nv_bfloat16& l) {
    h = __float2bfloat16(v);
    l = __float2bfloat16(v - __bfloat162float(h));
}

// ---------------------------------------------------------------------------
// fp32 -> bf16 hi/lo split (scale folded in)
// ---------------------------------------------------------------------------
__global__ void split_f32_kernel(const float* __restrict__ src,
                                 __nv_bfloat16* __restrict__ hi,
                                 __nv_bfloat16* __restrict__ lo,
                                 float scale, int n4) {
    int i = blockIdx.x * blockDim.x + threadIdx.x;
    if (i >= n4) return;
    float4 v = ((const float4*)src)[i];
    v.x *= scale; v.y *= scale; v.z *= scale; v.w *= scale;
    __nv_bfloat16 h0, h1, h2, h3, l0, l1, l2, l3;
    split1(v.x, h0, l0); split1(v.y, h1, l1);
    split1(v.z, h2, l2); split1(v.w, h3, l3);
    __nv_bfloat162* H = (__nv_bfloat162*)hi;
    __nv_bfloat162* L = (__nv_bfloat162*)lo;
    H[2*i]   = __halves2bfloat162(h0, h1);
    H[2*i+1] = __halves2bfloat162(h2, h3);
    L[2*i]   = __halves2bfloat162(l0, l1);
    L[2*i+1] = __halves2bfloat162(l2, l3);
}

// Batched weight splits: blockIdx.y selects the job
struct SplitJobs {
    const float* src[6];
    __nv_bfloat16* hi[6];
    __nv_bfloat16* lo[6];
    float scale[6];
};
__global__ void batch_split_kernel(SplitJobs J, int n4) {
    int i = blockIdx.x * blockDim.x + threadIdx.x;
    if (i >= n4) return;
    int j = blockIdx.y;
    float sc = J.scale[j];
    float4 v = ((const float4*)J.src[j])[i];
    v.x *= sc; v.y *= sc; v.z *= sc; v.w *= sc;
    __nv_bfloat16 h0, h1, h2, h3, l0, l1, l2, l3;
    split1(v.x, h0, l0); split1(v.y, h1, l1);
    split1(v.z, h2, l2); split1(v.w, h3, l3);
    __nv_bfloat162* H = (__nv_bfloat162*)J.hi[j];
    __nv_bfloat162* L = (__nv_bfloat162*)J.lo[j];
    H[2*i]   = __halves2bfloat162(h0, h1);
    H[2*i+1] = __halves2bfloat162(h2, h3);
    L[2*i]   = __halves2bfloat162(l0, l1);
    L[2*i+1] = __halves2bfloat162(l2, l3);
}

// Gather rows of x and split to bf16 hi/lo directly
__global__ void gather_split_kernel(const float* __restrict__ x,
                                    const int* __restrict__ idx,
                                    __nv_bfloat16* __restrict__ hi,
                                    __nv_bfloat16* __restrict__ lo) {
    int s = blockIdx.x;
    int b = blockIdx.y;
    int j = idx[s] & (SEQ - 1);
    const float4* src = (const float4*)&x[((size_t)b * SEQ + j) * DMODEL];
    size_t dbase = ((size_t)b * SEQ + s) * DMODEL;
    int t = threadIdx.x;   // 256 threads, 1 float4 each
    float4 v = src[t];
    __nv_bfloat16 h0, h1, h2, h3, l0, l1, l2, l3;
    split1(v.x, h0, l0); split1(v.y, h1, l1);
    split1(v.z, h2, l2); split1(v.w, h3, l3);
    __nv_bfloat162* H = (__nv_bfloat162*)&hi[dbase + t * 4];
    __nv_bfloat162* L = (__nv_bfloat162*)&lo[dbase + t * 4];
    H[0] = __halves2bfloat162(h0, h1);
    H[1] = __halves2bfloat162(h2, h3);
    L[0] = __halves2bfloat162(l0, l1);
    L[1] = __halves2bfloat162(l2, l3);
}

__global__ void combine_bias_kernel(const float* __restrict__ bk,
                                    const float* __restrict__ bbar,
                                    const float* __restrict__ bbeat,
                                    float* __restrict__ out) {
    int i = blockIdx.x * blockDim.x + threadIdx.x;
    if (i < DMODEL) out[i] = bk[i] + 0.2f * bbar[i] + 0.1f * bbeat[i];
}

// ---------------------------------------------------------------------------
// HMMA split-bf16 GEMM (R14-validated config): C = sum_t A_t @ B_t^T + bias
// CTA tile 128x128, K-chunk 64, 3-stage cp.async pipeline, 8 warps (2x4).
// ---------------------------------------------------------------------------
struct GemmParams {
    const __nv_bfloat16* Ahi[3];
    const __nv_bfloat16* Alo[3];
    const __nv_bfloat16* Bhi[3];
    const __nv_bfloat16* Blo[3];
    const float* bias;
    float* Cf;                 // optional fp32 output (may be null)
    __nv_bfloat16* Chi;        // optional split output (may be null)
    __nv_bfloat16* Clo;
    float cscale;              // scale folded into split output
    int nterms;
};
struct GemmTriple { GemmParams p[3]; };

#define GSTAGE_BYTES 65536            // 4 tiles x 16KB
#define GSMEM_TOTAL  (3 * GSTAGE_BYTES)

__device__ __forceinline__ void g_load_chunk(
    const GemmParams& P, int c, int s, uint32_t smem_u32,
    int bm, int bn, int tr, int sg)
{
    int term = c >> 4;
    int kc = c & 15;
    const __nv_bfloat16* M0 = P.Ahi[term];
    const __nv_bfloat16* M1 = P.Alo[term];
    const __nv_bfloat16* M2 = P.Bhi[term];
    const __nv_bfloat16* M3 = P.Blo[term];
    uint32_t sb = smem_u32 + s * GSTAGE_BYTES;
    int colel = kc * 64 + sg * 8;
    #pragma unroll
    for (int i = 0; i < 16; i++) {
        const int mat = i >> 2;
        const int row = (i & 3) * 32 + tr;
        const uint32_t soff = (uint32_t)mat * 16384u + (uint32_t)row * 128u
                              + (uint32_t)((sg ^ (row & 7)) * 16);
        const __nv_bfloat16* base = (mat == 0) ? M0 : (mat == 1) ? M1
                                   : (mat == 2) ? M2 : M3;
        const int grow = ((mat < 2) ? bm : bn) + row;
        const __nv_bfloat16* g = base + (size_t)grow * 1024 + colel;
        asm volatile("cp.async.cg.shared.global [%0], [%1], 16;"
                     :: "r"(sb + soff), "l"(g));
    }
    asm volatile("cp.async.commit_group;" ::: "memory");
}

__global__ __launch_bounds__(256, 1) void gemm_tc(GemmTriple T)
{
    extern __shared__ __align__(1024) char smem[];
    const uint32_t smem_u32 = smem_to_u32(smem);
    const GemmParams P = T.p[blockIdx.z];
    const int tid  = threadIdx.x;
    const int wid  = tid >> 5;
    const int lane = tid & 31;
    const int bm = blockIdx.y * 128;
    const int bn = blockIdx.x * 128;
    const int NC = P.nterms * 16;
    const int tr = tid >> 3;
    const int sg = tid & 7;
    const int wm = wid >> 2;
    const int wn = wid & 3;

    float acc[4][4][4];
    #pragma unroll
    for (int i = 0; i < 4; i++)
        #pragma unroll
        for (int j = 0; j < 4; j++)
            #pragma unroll
            for (int r = 0; r < 4; r++) acc[i][j][r] = 0.0f;

    const int arow = wm * 64 + (lane & 15);
    const int akc  = lane >> 4;
    const int brow = wn * 32 + ((lane >> 4) << 3) + (lane & 7);
    const int bkc  = (lane >> 3) & 1;

    g_load_chunk(P, 0, 0, smem_u32, bm, bn, tr, sg);
    g_load_chunk(P, 1, 1, smem_u32, bm, bn, tr, sg);
    g_load_chunk(P, 2, 2, smem_u32, bm, bn, tr, sg);

    for (int c = 0; c < NC; c++) {
        int s = c - (c / 3) * 3;
        if (c + 1 >= NC)      asm volatile("cp.async.wait_group 0;" ::: "memory");
        else if (c + 2 >= NC) asm volatile("cp.async.wait_group 1;" ::: "memory");
        else                  asm volatile("cp.async.wait_group 2;" ::: "memory");
        __syncthreads();

        const uint32_t sb  = smem_u32 + s * GSTAGE_BYTES;
        const uint32_t sAh = sb;
        const uint32_t sAl = sb + 16384;
        const uint32_t sBh = sb + 32768;
        const uint32_t sBl = sb + 49152;

        #pragma unroll
        for (int ks = 0; ks < 4; ks++) {
            const int k8 = ks * 2;
            uint32_t ah[4][4], al[4][4];
            #pragma unroll
            for (int mf = 0; mf < 4; mf++) {
                int row = arow + mf * 16;
                uint32_t off = (uint32_t)row * 128u
                             + (uint32_t)(((k8 + akc) ^ (row & 7)) << 4);
                ldsm_x4(ah[mf][0], ah[mf][1], ah[mf][2], ah[mf][3], sAh + off);
                ldsm_x4(al[mf][0], al[mf][1], al[mf][2], al[mf][3], sAl + off);
            }
            uint32_t bh[4][2], bl[4][2];
            #pragma unroll
            for (int pr = 0; pr < 2; pr++) {
                int row = pr * 16 + brow;
                uint32_t off = (uint32_t)row * 128u
                             + (uint32_t)(((k8 + bkc) ^ (row & 7)) << 4);
                ldsm_x4(bh[2*pr][0], bh[2*pr][1], bh[2*pr+1][0], bh[2*pr+1][1], sBh + off);
                ldsm_x4(bl[2*pr][0], bl[2*pr][1], bl[2*pr+1][0], bl[2*pr+1][1], sBl + off);
            }
            #pragma unroll
            for (int mf = 0; mf < 4; mf++)
                #pragma unroll
                for (int nf = 0; nf < 4; nf++) {
                    mma16816(acc[mf][nf], ah[mf][0], ah[mf][1], ah[mf][2], ah[mf][3],
                             bh[nf][0], bh[nf][1]);
                    mma16816(acc[mf][nf], ah[mf][0], ah[mf][1], ah[mf][2], ah[mf][3],
                             bl[nf][0], bl[nf][1]);
                    mma16816(acc[mf][nf], al[mf][0], al[mf][1], al[mf][2], al[mf][3],
                             bh[nf][0], bh[nf][1]);
                }
        }
        __syncthreads();
        if (c + 3 < NC)
            g_load_chunk(P, c + 3, s, smem_u32, bm, bn, tr, sg);
    }

    // Epilogue: v = acc + bias; optional fp32 store; optional bf16 hi/lo store
    const int r_in = lane >> 2;
    const int c_in = (lane & 3) * 2;
    #pragma unroll
    for (int mf = 0; mf < 4; mf++) {
        #pragma unroll
        for (int nf = 0; nf < 4; nf++) {
            int col = bn + wn * 32 + nf * 8 + c_in;
            float2 b2 = *(const float2*)&P.bias[col];
            int r1 = bm + wm * 64 + mf * 16 + r_in;
            float v00 = acc[mf][nf][0] + b2.x, v01 = acc[mf][nf][1] + b2.y;
            float v10 = acc[mf][nf][2] + b2.x, v11 = acc[mf][nf][3] + b2.y;
            size_t i0 = (size_t)r1 * 1024 + col;
            size_t i1 = (size_t)(r1 + 8) * 1024 + col;
            if (P.Cf) {
                *(float2*)&P.Cf[i0] = make_float2(v00, v01);
                *(float2*)&P.Cf[i1] = make_float2(v10, v11);
            }
            if (P.Chi) {
                float s00 = v00 * P.cscale, s01 = v01 * P.cscale;
                float s10 = v10 * P.cscale, s11 = v11 * P.cscale;
                __nv_bfloat16 h00, h01, h10, h11, l00, l01, l10, l11;
                split1(s00, h00, l00); split1(s01, h01, l01);
                split1(s10, h10, l10); split1(s11, h11, l11);
                *(__nv_bfloat162*)&P.Chi[i0] = __halves2bfloat162(h00, h01);
                *(__nv_bfloat162*)&P.Chi[i1] = __halves2bfloat162(h10, h11);
                *(__nv_bfloat162*)&P.Clo[i0] = __halves2bfloat162(l00, l01);
                *(__nv_bfloat162*)&P.Clo[i1] = __halves2bfloat162(l10, l11);
            }
        }
    }
}

// ---------------------------------------------------------------------------
// HMMA causal flash attention.
// V kept row-layout like K; PV B-fragments come from ldmatrix.x4.trans.
// Block = (64 q-rows, head, batch); 4 warps, each owns 16 q-rows.
// smem: Qhi|Qlo (16KB) + 2 stages x (Khi|Klo|Vhi|Vlo) (32KB each) = 80KB.
// ---------------------------------------------------------------------------
#define ATTN_SMEM (16384 + 2 * 32768)

__device__ __forceinline__ void attn_load_stage(
    uint32_t sbase,
    const __nv_bfloat16* __restrict__ Khi, const __nv_bfloat16* __restrict__ Klo,
    const __nv_bfloat16* __restrict__ Vhi, const __nv_bfloat16* __restrict__ Vlo,
    int b, int h, int kt, int tr, int sg)
{
    const size_t kbase = ((size_t)(b * SEQ + kt * 64)) * DMODEL + h * HD + sg * 8;
    #pragma unroll
    for (int rr = 0; rr < 4; rr++) {
        int row = rr * 16 + tr;
        uint32_t soff = (uint32_t)row * 128u + (uint32_t)((sg ^ (row & 7)) * 16);
        size_t gofs = kbase + (size_t)row * DMODEL;
        asm volatile("cp.async.cg.shared.global [%0], [%1], 16;"
                     :: "r"(sbase + soff),         "l"(Khi + gofs));
        asm volatile("cp.async.cg.shared.global [%0], [%1], 16;"
                     :: "r"(sbase + 8192 + soff),  "l"(Klo + gofs));
        asm volatile("cp.async.cg.shared.global [%0], [%1], 16;"
                     :: "r"(sbase + 16384 + soff), "l"(Vhi + gofs));
        asm volatile("cp.async.cg.shared.global [%0], [%1], 16;"
                     :: "r"(sbase + 24576 + soff), "l"(Vlo + gofs));
    }
    asm volatile("cp.async.commit_group;" ::: "memory");
}

__global__ __launch_bounds__(128, 1) void attn_mma(
    const __nv_bfloat16* __restrict__ Qhi, const __nv_bfloat16* __restrict__ Qlo,
    const __nv_bfloat16* __restrict__ Khi, const __nv_bfloat16* __restrict__ Klo,
    const __nv_bfloat16* __restrict__ Vhi, const __nv_bfloat16* __restrict__ Vlo,
    __nv_bfloat16* __restrict__ Ohi, __nv_bfloat16* __restrict__ Olo)
{
    extern __shared__ __align__(1024) char smem[];
    const uint32_t smem_u32 = smem_to_u32(smem);
    const int qb = blockIdx.x, h = blockIdx.y, b = blockIdx.z;
    const int tid = threadIdx.x, w = tid >> 5, lane = tid & 31;
    const int q0 = qb * 64;
    const int sg = tid & 7, tr = tid >> 3;

    {
        const size_t qbase = ((size_t)(b * SEQ + q0)) * DMODEL + h * HD + sg * 8;
        #pragma unroll
        for (int rr = 0; rr < 4; rr++) {
            int row = rr * 16 + tr;
            uint32_t soff = (uint32_t)row * 128u + (uint32_t)((sg ^ (row & 7)) * 16);
            asm volatile("cp.async.cg.shared.global [%0], [%1], 16;"
                         :: "r"(smem_u32 + soff),        "l"(Qhi + qbase + (size_t)row * DMODEL));
            asm volatile("cp.async.cg.shared.global [%0], [%1], 16;"
                         :: "r"(smem_u32 + 8192 + soff), "l"(Qlo + qbase + (size_t)row * DMODEL));
        }
        asm volatile("cp.async.commit_group;" ::: "memory");
    }
    attn_load_stage(smem_u32 + 16384, Khi, Klo, Vhi, Vlo, b, h, 0, tr, sg);

    uint32_t qh[4][4], ql[4][4];
    float o[8][4];
    #pragma unroll
    for (int nf = 0; nf < 8; nf++)
        #pragma unroll
        for (int e = 0; e < 4; e++) o[nf][e] = 0.0f;
    float m0 = -1e30f, m1 = -1e30f, l0 = 0.0f, l1 = 0.0f;

    const int rA   = (lane & 15);
    const int kcA  = lane >> 4;
    const int rB   = ((lane >> 4) << 3) + (lane & 7);
    const int kcB  = (lane >> 3) & 1;
    // trans-load lane components for V (PV B-fragments)
    const int rV   = ((lane >> 3) & 1) * 8 + (lane & 7);   // s-row within k16
    const int gV   = lane >> 4;                            // 16B group within d16

    for (int kt = 0; kt <= qb; kt++) {
        if (kt + 1 <= qb)
            attn_load_stage(smem_u32 + 16384 + ((kt + 1) & 1) * 32768,
                            Khi, Klo, Vhi, Vlo, b, h, kt + 1, tr, sg);
        if (kt + 1 <= qb) asm volatile("cp.async.wait_group 1;" ::: "memory");
        else              asm volatile("cp.async.wait_group 0;" ::: "memory");
        __syncthreads();

        if (kt == 0) {
            #pragma unroll
            for (int ks = 0; ks < 4; ks++) {
                int row = w * 16 + rA;
                int k8 = ks * 2 + kcA;
                uint32_t off = (uint32_t)row * 128u + (uint32_t)((k8 ^ (row & 7)) << 4);
                ldsm_x4(qh[ks][0], qh[ks][1], qh[ks][2], qh[ks][3], smem_u32 + off);
                ldsm_x4(ql[ks][0], ql[ks][1], ql[ks][2], ql[ks][3], smem_u32 + 8192 + off);
            }
        }

        const uint32_t sbase = smem_u32 + 16384 + (kt & 1) * 32768;
        const uint32_t sKh = sbase, sKl = sbase + 8192;
        const uint32_t sVh = sbase + 16384, sVl = sbase + 24576;

        float s[8][4];
        #pragma unroll
        for (int nf = 0; nf < 8; nf++)
            #pragma unroll
            for (int e = 0; e < 4; e++) s[nf][e] = 0.0f;

        #pragma unroll
        for (int ks = 0; ks < 4; ks++) {
            const int k8 = ks * 2;
            uint32_t bh[8][2], bl[8][2];
            #pragma unroll
            for (int pr = 0; pr < 4; pr++) {
                int row = pr * 16 + rB;
                uint32_t off = (uint32_t)row * 128u
                             + (uint32_t)(((k8 + kcB) ^ (row & 7)) << 4);
                ldsm_x4(bh[2*pr][0], bh[2*pr][1], bh[2*pr+1][0], bh[2*pr+1][1], sKh + off);
                ldsm_x4(bl[2*pr][0], bl[2*pr][1], bl[2*pr+1][0], bl[2*pr+1][1], sKl + off);
            }
            #pragma unroll
            for (int nf = 0; nf < 8; nf++) {
                mma16816(s[nf], qh[ks][0], qh[ks][1], qh[ks][2], qh[ks][3], bh[nf][0], bh[nf][1]);
                mma16816(s[nf], qh[ks][0], qh[ks][1], qh[ks][2], qh[ks][3], bl[nf][0], bl[nf][1]);
                mma16816(s[nf], ql[ks][0], ql[ks][1], ql[ks][2], ql[ks][3], bh[nf][0], bh[nf][1]);
            }
        }

        if (kt == qb) {
            const int col0 = kt * 64 + 2 * (lane & 3);
            const int row0 = q0 + w * 16 + (lane >> 2);
            #pragma unroll
            for (int nf = 0; nf < 8; nf++) {
                int key = col0 + nf * 8;
                if (key     > row0)     s[nf][0] = -1e30f;
                if (key + 1 > row0)     s[nf][1] = -1e30f;
                if (key     > row0 + 8) s[nf][2] = -1e30f;
                if (key + 1 > row0 + 8) s[nf][3] = -1e30f;
            }
        }

        float mx0 = -1e30f, mx1 = -1e30f;
        #pragma unroll
        for (int nf = 0; nf < 8; nf++) {
            mx0 = fmaxf(mx0, fmaxf(s[nf][0], s[nf][1]));
            mx1 = fmaxf(mx1, fmaxf(s[nf][2], s[nf][3]));
        }
        mx0 = fmaxf(mx0, __shfl_xor_sync(0xFFFFFFFFu, mx0, 1));
        mx0 = fmaxf(mx0, __shfl_xor_sync(0xFFFFFFFFu, mx0, 2));
        mx1 = fmaxf(mx1, __shfl_xor_sync(0xFFFFFFFFu, mx1, 1));
        mx1 = fmaxf(mx1, __shfl_xor_sync(0xFFFFFFFFu, mx1, 2));
        float mn0 = fmaxf(m0, mx0);
        float mn1 = fmaxf(m1, mx1);
        float corr0 = __expf(m0 - mn0);
        float corr1 = __expf(m1 - mn1);
        m0 = mn0; m1 = mn1;

        float sum0 = 0.0f, sum1 = 0.0f;
        uint32_t pr_hi[8], pr8_hi[8], pr_lo[8], pr8_lo[8];
        #pragma unroll
        for (int nf = 0; nf < 8; nf++) {
            float p0 = __expf(s[nf][0] - mn0);
            float p1 = __expf(s[nf][1] - mn0);
            float p2 = __expf(s[nf][2] - mn1);
            float p3 = __expf(s[nf][3] - mn1);
            sum0 += p0 + p1;
            sum1 += p2 + p3;
            __nv_bfloat16 h0 = __float2bfloat16(p0);
            __nv_bfloat16 h1 = __float2bfloat16(p1);
            __nv_bfloat16 h2 = __float2bfloat16(p2);
            __nv_bfloat16 h3 = __float2bfloat16(p3);
            __nv_bfloat162 t0 = __halves2bfloat162(h0, h1);
            __nv_bfloat162 t1 = __halves2bfloat162(h2, h3);
            pr_hi[nf]  = *reinterpret_cast<uint32_t*>(&t0);
            pr8_hi[nf] = *reinterpret_cast<uint32_t*>(&t1);
            pr_lo[nf]  = pack_bf2(p0 - __bfloat162float(h0), p1 - __bfloat162float(h1));
            pr8_lo[nf] = pack_bf2(p2 - __bfloat162float(h2), p3 - __bfloat162float(h3));
        }
        sum0 += __shfl_xor_sync(0xFFFFFFFFu, sum0, 1);
        sum0 += __shfl_xor_sync(0xFFFFFFFFu, sum0, 2);
        sum1 += __shfl_xor_sync(0xFFFFFFFFu, sum1, 1);
        sum1 += __shfl_xor_sync(0xFFFFFFFFu, sum1, 2);
        l0 = l0 * corr0 + sum0;
        l1 = l1 * corr1 + sum1;
        #pragma unroll
        for (int nf = 0; nf < 8; nf++) {
            o[nf][0] *= corr0; o[nf][1] *= corr0;
            o[nf][2] *= corr1; o[nf][3] *= corr1;
        }

        // ---- O += P @ V via trans-loads of row-layout V tiles ----
        #pragma unroll
        for (int ks = 0; ks < 4; ks++) {
            uint32_t vh[8][2], vl[8][2];
            #pragma unroll
            for (int pr = 0; pr < 4; pr++) {
                int row = ks * 16 + rV;           // s-row in tile
                int g   = pr * 2 + gV;            // 16B group = d/8
                uint32_t off = (uint32_t)row * 128u
                             + (uint32_t)((g ^ (row & 7)) << 4);
                ldsm_x4_t(vh[2*pr][0], vh[2*pr][1], vh[2*pr+1][0], vh[2*pr+1][1], sVh + off);
                ldsm_x4_t(vl[2*pr][0], vl[2*pr][1], vl[2*pr+1][0], vl[2*pr+1][1], sVl + off);
            }
            uint32_t a0h = pr_hi[2*ks],  a1h = pr8_hi[2*ks];
            uint32_t a2h = pr_hi[2*ks+1], a3h = pr8_hi[2*ks+1];
            uint32_t a0l = pr_lo[2*ks],  a1l = pr8_lo[2*ks];
            uint32_t a2l = pr_lo[2*ks+1], a3l = pr8_lo[2*ks+1];
            #pragma unroll
            for (int nf = 0; nf < 8; nf++) {
                mma16816(o[nf], a0h, a1h, a2h, a3h, vh[nf][0], vh[nf][1]);
                mma16816(o[nf], a0h, a1h, a2h, a3h, vl[nf][0], vl[nf][1]);
                mma16816(o[nf], a0l, a1l, a2l, a3l, vh[nf][0], vh[nf][1]);
            }
        }
        __syncthreads();
    }

    // Epilogue: normalize and write bf16 hi/lo split directly
    float inv0 = 1.0f / l0;
    float inv1 = 1.0f / l1;
    int row = q0 + w * 16 + (lane >> 2);
    size_t base0 = ((size_t)(b * SEQ + row)) * DMODEL + h * HD;
    #pragma unroll
    for (int nf = 0; nf < 8; nf++) {
        int col = nf * 8 + 2 * (lane & 3);
        float v00 = o[nf][0] * inv0, v01 = o[nf][1] * inv0;
        float v10 = o[nf][2] * inv1, v11 = o[nf][3] * inv1;
        __nv_bfloat16 h00, h01, h10, h11, l00, l01, l10, l11;
        split1(v00, h00, l00); split1(v01, h01, l01);
        split1(v10, h10, l10); split1(v11, h11, l11);
        size_t i0 = base0 + col;
        size_t i1 = base0 + (size_t)8 * DMODEL + col;
        *(__nv_bfloat162*)&Ohi[i0] = __halves2bfloat162(h00, h01);
        *(__nv_bfloat162*)&Ohi[i1] = __halves2bfloat162(h10, h11);
        *(__nv_bfloat162*)&Olo[i0] = __halves2bfloat162(l00, l01);
        *(__nv_bfloat162*)&Olo[i1] = __halves2bfloat162(l10, l11);
    }
}

// ---------------------------------------------------------------------------
// Launch
// ---------------------------------------------------------------------------
static float* sym_f(const void* symbol) {
    void* p = nullptr;
    cudaGetSymbolAddress(&p, (const void*)symbol);
    return (float*)p;
}

extern "C" void kernel_launch(void* const* d_in, const int* in_sizes, int n_in,
                              void* d_out, int out_size) {
    const float* x      = (const float*)d_in[0];
    const int* bar      = (const int*)d_in[2];
    const int* beat     = (const int*)d_in[3];
    const float* Wq = (const float*)d_in[4];
    const float* bq = (const float*)d_in[5];
    const float* Wk = (const float*)d_in[6];
    const float* bk = (const float*)d_in[7];
    const float* Wv = (const float*)d_in[8];
    const float* bv = (const float*)d_in[9];
    const float* Wbar  = (const float*)d_in[10];
    const float* bbar  = (const float*)d_in[11];
    const float* Wbeat = (const float*)d_in[12];
    const float* bbeat = (const float*)d_in[13];
    const float* Wo = (const float*)d_in[14];
    const float* bo = (const float*)d_in[15];
    float* out = (float*)d_out;

    float* biasKp = sym_f(g_biasK);

    __nv_bfloat16 *xhi, *xlo, *barhi, *barlo, *beathi, *beatlo, *aohi, *aolo;
    __nv_bfloat16 *wqhi, *wqlo, *wkhi, *wklo, *wvhi, *wvlo;
    __nv_bfloat16 *wbarhi, *wbarlo, *wbeathi, *wbeatlo, *wohi, *wolo;
    __nv_bfloat16 *qshi, *qslo, *kshi, *kslo, *vshi, *vslo;
    cudaGetSymbolAddress((void**)&xhi, g_xhi);     cudaGetSymbolAddress((void**)&xlo, g_xlo);
    cudaGetSymbolAddress((void**)&barhi, g_barhi); cudaGetSymbolAddress((void**)&barlo, g_barlo);
    cudaGetSymbolAddress((void**)&beathi, g_beathi); cudaGetSymbolAddress((void**)&beatlo, g_beatlo);
    cudaGetSymbolAddress((void**)&aohi, g_aohi);   cudaGetSymbolAddress((void**)&aolo, g_aolo);
    cudaGetSymbolAddress((void**)&wqhi, g_Wqhi);   cudaGetSymbolAddress((void**)&wqlo, g_Wqlo);
    cudaGetSymbolAddress((void**)&wkhi, g_Wkhi);   cudaGetSymbolAddress((void**)&wklo, g_Wklo);
    cudaGetSymbolAddress((void**)&wvhi, g_Wvhi);   cudaGetSymbolAddress((void**)&wvlo, g_Wvlo);
    cudaGetSymbolAddress((void**)&wbarhi, g_Wbarhi); cudaGetSymbolAddress((void**)&wbarlo, g_Wbarlo);
    cudaGetSymbolAddress((void**)&wbeathi, g_Wbeathi); cudaGetSymbolAddress((void**)&wbeatlo, g_Wbeatlo);
    cudaGetSymbolAddress((void**)&wohi, g_Wohi);   cudaGetSymbolAddress((void**)&wolo, g_Wolo);
    cudaGetSymbolAddress((void**)&qshi, g_Qshi);   cudaGetSymbolAddress((void**)&qslo, g_Qslo);
    cudaGetSymbolAddress((void**)&kshi, g_Kshi);   cudaGetSymbolAddress((void**)&kslo, g_Kslo);
    cudaGetSymbolAddress((void**)&vshi, g_Vshi);   cudaGetSymbolAddress((void**)&vslo, g_Vslo);

    cudaFuncSetAttribute(gemm_tc, cudaFuncAttributeMaxDynamicSharedMemorySize, GSMEM_TOTAL);
    cudaFuncSetAttribute(attn_mma, cudaFuncAttributeMaxDynamicSharedMemorySize, ATTN_SMEM);

    const int NACT = MTOT * DMODEL / 4;
    const int NW   = DMODEL * DMODEL / 4;

    // Conversions: x split, gathers, 6 weight splits (one batched launch), bias combine
    split_f32_kernel<<<(NACT + 255) / 256, 256>>>(x, xhi, xlo, 1.0f, NACT);
    gather_split_kernel<<<dim3(SEQ, BATCH), 256>>>(x, bar,  barhi,  barlo);
    gather_split_kernel<<<dim3(SEQ, BATCH), 256>>>(x, beat, beathi, beatlo);
    {
        SplitJobs J;
        J.src[0] = Wq;    J.hi[0] = wqhi;    J.lo[0] = wqlo;    J.scale[0] = 1.0f;
        J.src[1] = Wk;    J.hi[1] = wkhi;    J.lo[1] = wklo;    J.scale[1] = 1.0f;
        J.src[2] = Wv;    J.hi[2] = wvhi;    J.lo[2] = wvlo;    J.scale[2] = 1.0f;
        J.src[3] = Wbar;  J.hi[3] = wbarhi;  J.lo[3] = wbarlo;  J.scale[3] = 0.2f;
        J.src[4] = Wbeat; J.hi[4] = wbeathi; J.lo[4] = wbeatlo; J.scale[4] = 0.1f;
        J.src[5] = Wo;    J.hi[5] = wohi;    J.lo[5] = wolo;    J.scale[5] = 1.0f;
        batch_split_kernel<<<dim3((NW + 255) / 256, 6), 256>>>(J, NW);
    }
    combine_bias_kernel<<<4, 256>>>(bk, bbar, bbeat, biasKp);

    // Fused Q/V/K_eff projections (grid.z selects), split outputs written directly
    {
        GemmTriple T = {};
        // z=0: Q -> split only (scale 1/8 folded)
        T.p[0].Ahi[0] = xhi; T.p[0].Alo[0] = xlo;
        T.p[0].Bhi[0] = wqhi; T.p[0].Blo[0] = wqlo;
        T.p[0].bias = bq; T.p[0].Cf = nullptr;
        T.p[0].Chi = qshi; T.p[0].Clo = qslo; T.p[0].cscale = 0.125f;
        T.p[0].nterms = 1;
        // z=1: V -> split only (row layout, consumed via trans-ldmatrix)
        T.p[1].Ahi[0] = xhi; T.p[1].Alo[0] = xlo;
        T.p[1].Bhi[0] = wvhi; T.p[1].Blo[0] = wvlo;
        T.p[1].bias = bv; T.p[1].Cf = nullptr;
        T.p[1].Chi = vshi; T.p[1].Clo = vslo; T.p[1].cscale = 1.0f;
        T.p[1].nterms = 1;
        // z=2: K_eff (3 terms) -> split only
        T.p[2].Ahi[0] = xhi;    T.p[2].Alo[0] = xlo;
        T.p[2].Bhi[0] = wkhi;   T.p[2].Blo[0] = wklo;
        T.p[2].Ahi[1] = barhi;  T.p[2].Alo[1] = barlo;
        T.p[2].Bhi[1] = wbarhi; T.p[2].Blo[1] = wbarlo;
        T.p[2].Ahi[2] = beathi; T.p[2].Alo[2] = beatlo;
        T.p[2].Bhi[2] = wbeathi; T.p[2].Blo[2] = wbeatlo;
        T.p[2].bias = biasKp; T.p[2].Cf = nullptr;
        T.p[2].Chi = kshi; T.p[2].Clo = kslo; T.p[2].cscale = 1.0f;
        T.p[2].nterms = 3;
        gemm_tc<<<dim3(8, 32, 3), 256, GSMEM_TOTAL>>>(T);
    }

    // HMMA causal attention -> writes ao hi/lo splits directly
    attn_mma<<<dim3(SEQ / 64, HEADS, BATCH), 128, ATTN_SMEM>>>(
        qshi, qslo, kshi, kslo, vshi, vslo, aohi, aolo);

    // Output projection: out = AO @ Wo^T + bo (fp32 to d_out)
    {
        GemmTriple T = {};
        T.p[0].Ahi[0] = aohi; T.p[0].Alo[0] = aolo;
        T.p[0].Bhi[0] = wohi; T.p[0].Blo[0] = wolo;
        T.p[0].bias = bo; T.p[0].Cf = out;
        T.p[0].Chi = nullptr; T.p[0].Clo = nullptr; T.p[0].cscale = 1.0f;
        T.p[0].nterms = 1;
        gemm_tc<<<dim3(8, 32, 1), 256, GSMEM_TOTAL>>>(T);
    }
}